// round 5
// baseline (speedup 1.0000x reference)
#include <cuda_runtime.h>
#include <cstdint>

#define NN 100000
#define EE 800000
#define HH 64
#define QMM 32
#define BB 100
#define LL 4
#define EPS_BN 1e-5f

// ---------------- scratch (static __device__ — no allocations allowed) ----------------
__device__ float g_feat[(size_t)EE * 64];   // [z_re(32) | z_im(32)] per edge, 204.8 MB
__device__ float g_msg[(size_t)EE * 64];    // per-edge messages, 204.8 MB
__device__ int   g_eg[EE];                  // graph id per edge
__device__ int   g_deg[NN];                 // in-degree
__device__ int   g_rowptr[NN + 1];          // CSR row pointers (by dst)
__device__ int   g_cur[NN];                 // fill cursors
__device__ int   g_eidx[EE];                // CSR edge ids
__device__ float g_y1[(size_t)NN * 64];     // pre-BN1 activations
__device__ float g_y2[(size_t)NN * 64];     // pre-BN2 activations
__device__ float g_xb[(size_t)NN * 64];     // node feature ping buffer
__device__ float g_wtab[BB * QMM];          // per-graph eigen weights w[B,Q*M]
__device__ float g_Wc[128 * 64];            // fused edge weight [W1;W2]
__device__ float g_bc[64];                  // fused edge bias
__device__ float g_stats[256];              // [bn1 sum | bn1 sq | bn2 sum | bn2 sq]

// ---------------- f32x2 packed math helpers (Blackwell) ----------------
__device__ __forceinline__ unsigned long long pack2(float a, float b) {
    unsigned long long r;
    asm("mov.b64 %0, {%1, %2};" : "=l"(r) : "f"(a), "f"(b));
    return r;
}
__device__ __forceinline__ void ffma2(unsigned long long& d, unsigned long long a, unsigned long long b) {
    asm("fma.rn.f32x2 %0, %1, %2, %0;" : "+l"(d) : "l"(a), "l"(b));
}
__device__ __forceinline__ float2 unpack2(unsigned long long v) {
    float2 r;
    asm("mov.b64 {%0, %1}, %2;" : "=f"(r.x), "=f"(r.y) : "l"(v));
    return r;
}

// ---------------- one-time precompute ----------------

// z = pe[src] * conj(pe[dst]); one warp per edge, lane = (q,m)
__global__ __launch_bounds__(256) void z_kernel(const float* __restrict__ pe,
                                                const int* __restrict__ ei,
                                                const int* __restrict__ batch) {
    int e = blockIdx.x * 8 + (threadIdx.x >> 5);
    int qm = threadIdx.x & 31;
    int src = ei[e];
    int dst = ei[EE + e];
    const float2* pe2 = (const float2*)pe;
    float2 zs = pe2[(size_t)src * 32 + qm];
    float2 zd = pe2[(size_t)dst * 32 + qm];
    float zr = zs.x * zd.x + zs.y * zd.y;
    float zi = zs.y * zd.x - zs.x * zd.y;
    g_feat[(size_t)e * 64 + qm] = zr;
    g_feat[(size_t)e * 64 + 32 + qm] = zi;
    if (qm == 0) g_eg[e] = batch[src];
}

__global__ void copy_pe_kernel(const float* __restrict__ pe, float* __restrict__ out) {
    size_t i = (size_t)blockIdx.x * 256 + threadIdx.x;   // < N*16 float4
    ((float4*)out)[i] = ((const float4*)pe)[i];
}

// ---- CSR build (dst is layer-invariant) ----
__global__ void deg_zero_kernel() {
    int i = blockIdx.x * 256 + threadIdx.x;
    if (i < NN) g_deg[i] = 0;
}
__global__ void deg_count_kernel(const int* __restrict__ ei) {
    int e = blockIdx.x * 256 + threadIdx.x;
    if (e < EE) atomicAdd(&g_deg[ei[EE + e]], 1);
}
__global__ __launch_bounds__(1024) void scan_kernel() {
    __shared__ int sSum[1024];
    int t = threadIdx.x;
    const int CH = (NN + 1023) / 1024;
    int lo = t * CH; if (lo > NN) lo = NN;
    int hi = lo + CH; if (hi > NN) hi = NN;
    int s = 0;
    for (int i = lo; i < hi; i++) s += g_deg[i];
    sSum[t] = s;
    __syncthreads();
    for (int off = 1; off < 1024; off <<= 1) {
        int v = (t >= off) ? sSum[t - off] : 0;
        __syncthreads();
        sSum[t] += v;
        __syncthreads();
    }
    int base = (t == 0) ? 0 : sSum[t - 1];
    for (int i = lo; i < hi; i++) {
        g_rowptr[i] = base;
        g_cur[i] = base;
        base += g_deg[i];
    }
    if (t == 1023) g_rowptr[NN] = sSum[1023];
}
__global__ void fill_kernel(const int* __restrict__ ei) {
    int e = blockIdx.x * 256 + threadIdx.x;
    if (e >= EE) return;
    int pos = atomicAdd(&g_cur[ei[EE + e]], 1);
    g_eidx[pos] = e;
}

// ---------------- per-layer small kernels ----------------

// eigenvalue MLP: w[b,qm] = phi(Lam[b,qm]); block 0 also zeroes BN stats
__global__ void phi_kernel(const float* __restrict__ Lam, const float* __restrict__ pw1,
                           const float* __restrict__ pb1, const float* __restrict__ pw2,
                           const float* __restrict__ pb2, int l) {
    if (blockIdx.x == 0) g_stats[threadIdx.x] = 0.f;
    int i = blockIdx.x * 256 + threadIdx.x;
    if (i >= BB * QMM) return;
    float lam = Lam[i];
    float s = pb2[l];
#pragma unroll
    for (int j = 0; j < 16; j++) {
        float h = fmaxf(lam * pw1[l * 16 + j] + pb1[l * 16 + j], 0.f);
        s += h * pw2[l * 16 + j];
    }
    g_wtab[i] = s;
}

// W1 = enc_w@lin_w ; W2 = lin_w ; bc = enc_b@lin_w + lin_b
__global__ void fuse_kernel(const float* __restrict__ enc_w, const float* __restrict__ enc_b,
                            const float* __restrict__ lin_w, const float* __restrict__ lin_b, int l) {
    int k = blockIdx.x;    // 0..63
    int h = threadIdx.x;   // 0..63
    const float* ew = enc_w + (size_t)l * 64 * 64;
    const float* lw = lin_w + (size_t)l * 64 * 64;
    float s = 0.f;
    for (int j = 0; j < 64; j++) s += ew[k * 64 + j] * lw[j * 64 + h];
    g_Wc[k * 64 + h] = s;
    g_Wc[(64 + k) * 64 + h] = lw[k * 64 + h];
    if (k == 0) {
        float b = lin_b[l * 64 + h];
        for (int j = 0; j < 64; j++) b += enc_b[l * 64 + j] * lw[j * 64 + h];
        g_bc[h] = b;
    }
}

// ---------------- edge kernel: msg = relu([feat*we | ea] @ Wc + bc + x[src]) ----------------
// 64 edges per block, 256 threads, 16 edges per thread (8 f32x2 accumulators).
__global__ __launch_bounds__(256) void edge_kernel(const float* __restrict__ edge_attr,
                                                   const float* __restrict__ xcur,
                                                   const int* __restrict__ ei) {
    __shared__ float sW[64 * 64];    // 16 KB, per-phase W
    __shared__ float sA[64 * 64];    // 16 KB, k-major [k][edge]
    __shared__ int sSrc[64], sG[64];
    __shared__ float sB[64];
    int t = threadIdx.x;
    int e0 = blockIdx.x * 64;
    int e_loc = t & 63, part = t >> 6;   // 64 edges x 4 k-chunks(16)
    int e = e0 + e_loc;
    int k0 = part * 16;

    // phase-1 W (rows 0..63) + per-edge metadata
    {
        const float4* Wv = (const float4*)g_Wc;
        float4* sWv = (float4*)sW;
#pragma unroll
        for (int i = 0; i < 4; i++) sWv[t + 256 * i] = Wv[t + 256 * i];
    }
    if (t < 64) {
        sSrc[t] = ei[e0 + t];
        sG[t] = g_eg[e0 + t];
        sB[t] = g_bc[t];
    }
    __syncthreads();   // sG visible for staging

    // phase-1 staging: feat * we (k = 0..63)
    {
        const float* wv = g_wtab + sG[e_loc] * QMM;
        int m0 = k0 & 31;
#pragma unroll
        for (int c = 0; c < 4; c++) {
            float4 f = *(const float4*)(g_feat + (size_t)e * 64 + k0 + c * 4);
            sA[(k0 + c * 4 + 0) * 64 + e_loc] = f.x * wv[m0 + c * 4 + 0];
            sA[(k0 + c * 4 + 1) * 64 + e_loc] = f.y * wv[m0 + c * 4 + 1];
            sA[(k0 + c * 4 + 2) * 64 + e_loc] = f.z * wv[m0 + c * 4 + 2];
            sA[(k0 + c * 4 + 3) * 64 + e_loc] = f.w * wv[m0 + c * 4 + 3];
        }
    }
    __syncthreads();

    int tx = t & 63, ty = t >> 6;   // channel, edge-16-group
    unsigned long long acc[8] = {0ull,0ull,0ull,0ull,0ull,0ull,0ull,0ull};
#pragma unroll 8
    for (int k = 0; k < 64; k++) {
        float w = sW[k * 64 + tx];
        unsigned long long w2 = pack2(w, w);
        const ulonglong2* ap = (const ulonglong2*)(sA + k * 64 + ty * 16);
        ulonglong2 a01 = ap[0], a23 = ap[1], a45 = ap[2], a67 = ap[3];
        ffma2(acc[0], a01.x, w2);
        ffma2(acc[1], a01.y, w2);
        ffma2(acc[2], a23.x, w2);
        ffma2(acc[3], a23.y, w2);
        ffma2(acc[4], a45.x, w2);
        ffma2(acc[5], a45.y, w2);
        ffma2(acc[6], a67.x, w2);
        ffma2(acc[7], a67.y, w2);
    }
    __syncthreads();

    // phase-2: W rows 64..127 + edge_attr staging
    {
        const float4* Wv = (const float4*)(g_Wc + 64 * 64);
        float4* sWv = (float4*)sW;
#pragma unroll
        for (int i = 0; i < 4; i++) sWv[t + 256 * i] = Wv[t + 256 * i];
    }
    {
#pragma unroll
        for (int c = 0; c < 4; c++) {
            float4 f = *(const float4*)(edge_attr + (size_t)e * 64 + k0 + c * 4);
            sA[(k0 + c * 4 + 0) * 64 + e_loc] = f.x;
            sA[(k0 + c * 4 + 1) * 64 + e_loc] = f.y;
            sA[(k0 + c * 4 + 2) * 64 + e_loc] = f.z;
            sA[(k0 + c * 4 + 3) * 64 + e_loc] = f.w;
        }
    }
    __syncthreads();
#pragma unroll 8
    for (int k = 0; k < 64; k++) {
        float w = sW[k * 64 + tx];
        unsigned long long w2 = pack2(w, w);
        const ulonglong2* ap = (const ulonglong2*)(sA + k * 64 + ty * 16);
        ulonglong2 a01 = ap[0], a23 = ap[1], a45 = ap[2], a67 = ap[3];
        ffma2(acc[0], a01.x, w2);
        ffma2(acc[1], a01.y, w2);
        ffma2(acc[2], a23.x, w2);
        ffma2(acc[3], a23.y, w2);
        ffma2(acc[4], a45.x, w2);
        ffma2(acc[5], a45.y, w2);
        ffma2(acc[6], a67.x, w2);
        ffma2(acc[7], a67.y, w2);
    }

    float b = sB[tx];
#pragma unroll
    for (int p = 0; p < 8; p++) {
        float2 v = unpack2(acc[p]);
        int ea = ty * 16 + p * 2;
        float vA = fmaxf(v.x + b + xcur[(size_t)sSrc[ea] * 64 + tx], 0.f);
        float vB = fmaxf(v.y + b + xcur[(size_t)sSrc[ea + 1] * 64 + tx], 0.f);
        g_msg[(size_t)(e0 + ea) * 64 + tx] = vA;
        g_msg[(size_t)(e0 + ea + 1) * 64 + tx] = vB;
    }
}

// ---------------- node kernels ----------------

// y1 = (x + gather(msg)) @ mlp_w1 + b1 ; accumulate BN1 column stats
__global__ __launch_bounds__(256) void nodeA_kernel(const float* __restrict__ xcur,
                                                    const float* __restrict__ W,
                                                    const float* __restrict__ bias, int l) {
    __shared__ float sW[64 * 64];
    __shared__ float sA[64 * 32];
    __shared__ float sRs[256], sRq[256];
    int t = threadIdx.x;
    int n0 = blockIdx.x * 32;
    {
        const float4* Wv = (const float4*)(W + (size_t)l * 4096);
        float4* sWv = (float4*)sW;
#pragma unroll
        for (int i = 0; i < 4; i++) sWv[t + 256 * i] = Wv[t + 256 * i];
    }
    int n_loc = t & 31, part = t >> 5;
    int k0 = part * 8;
    {
        int n = n0 + n_loc;
        size_t base = (size_t)n * 64 + k0;
        float4 a0 = *(const float4*)(xcur + base);
        float4 a1 = *(const float4*)(xcur + base + 4);
        int rs = g_rowptr[n], re = g_rowptr[n + 1];
        for (int j = rs; j < re; j++) {
            int e = g_eidx[j];
            const float4* m = (const float4*)(g_msg + (size_t)e * 64 + k0);
            float4 m0 = m[0], m1 = m[1];
            a0.x += m0.x; a0.y += m0.y; a0.z += m0.z; a0.w += m0.w;
            a1.x += m1.x; a1.y += m1.y; a1.z += m1.z; a1.w += m1.w;
        }
        sA[(k0 + 0) * 32 + n_loc] = a0.x;
        sA[(k0 + 1) * 32 + n_loc] = a0.y;
        sA[(k0 + 2) * 32 + n_loc] = a0.z;
        sA[(k0 + 3) * 32 + n_loc] = a0.w;
        sA[(k0 + 4) * 32 + n_loc] = a1.x;
        sA[(k0 + 5) * 32 + n_loc] = a1.y;
        sA[(k0 + 6) * 32 + n_loc] = a1.z;
        sA[(k0 + 7) * 32 + n_loc] = a1.w;
    }
    __syncthreads();

    int tx = t & 63, ty = t >> 6;
    unsigned long long acc[4] = {0ull, 0ull, 0ull, 0ull};
#pragma unroll 8
    for (int k = 0; k < 64; k++) {
        float w = sW[k * 64 + tx];
        unsigned long long w2 = pack2(w, w);
        const ulonglong2* ap = (const ulonglong2*)(sA + k * 32 + ty * 8);
        ulonglong2 a01 = ap[0];
        ulonglong2 a23 = ap[1];
        ffma2(acc[0], a01.x, w2);
        ffma2(acc[1], a01.y, w2);
        ffma2(acc[2], a23.x, w2);
        ffma2(acc[3], a23.y, w2);
    }
    float bb = bias[l * 64 + tx];
    float s = 0.f, q = 0.f;
#pragma unroll
    for (int p = 0; p < 4; p++) {
        float2 v = unpack2(acc[p]);
        int na = ty * 8 + p * 2;
        float yA = v.x + bb, yB = v.y + bb;
        g_y1[(size_t)(n0 + na) * 64 + tx] = yA;
        g_y1[(size_t)(n0 + na + 1) * 64 + tx] = yB;
        s += yA + yB;
        q += yA * yA + yB * yB;
    }
    sRs[t] = s;
    sRq[t] = q;
    __syncthreads();
    if (t < 64) {
        s = sRs[t] + sRs[64 + t] + sRs[128 + t] + sRs[192 + t];
        q = sRq[t] + sRq[64 + t] + sRq[128 + t] + sRq[192 + t];
        atomicAdd(&g_stats[t], s);
        atomicAdd(&g_stats[64 + t], q);
    }
}

// y2 = relu(BN1(y1)) @ mlp_w2 + b2 ; accumulate BN2 column stats
__global__ __launch_bounds__(256) void nodeB_kernel(const float* __restrict__ W,
                                                    const float* __restrict__ bias,
                                                    const float* __restrict__ bg,
                                                    const float* __restrict__ bnb, int l) {
    __shared__ float sW[64 * 64];
    __shared__ float sA[64 * 32];
    __shared__ float sSc[64], sSh[64];
    __shared__ float sRs[256], sRq[256];
    int t = threadIdx.x;
    int n0 = blockIdx.x * 32;
    {
        const float4* Wv = (const float4*)(W + (size_t)l * 4096);
        float4* sWv = (float4*)sW;
#pragma unroll
        for (int i = 0; i < 4; i++) sWv[t + 256 * i] = Wv[t + 256 * i];
    }
    if (t < 64) {
        float mu = g_stats[t] * (1.0f / NN);
        float var = g_stats[64 + t] * (1.0f / NN) - mu * mu;
        float rs = rsqrtf(var + EPS_BN);
        float sc = rs * bg[l * 64 + t];
        sSc[t] = sc;
        sSh[t] = bnb[l * 64 + t] - mu * sc;
    }
    __syncthreads();
    int n_loc = t & 31, part = t >> 5;
    int k0 = part * 8;
    {
        size_t base = (size_t)(n0 + n_loc) * 64 + k0;
        float4 y0 = *(const float4*)(g_y1 + base);
        float4 y1v = *(const float4*)(g_y1 + base + 4);
        sA[(k0 + 0) * 32 + n_loc] = fmaxf(y0.x * sSc[k0 + 0] + sSh[k0 + 0], 0.f);
        sA[(k0 + 1) * 32 + n_loc] = fmaxf(y0.y * sSc[k0 + 1] + sSh[k0 + 1], 0.f);
        sA[(k0 + 2) * 32 + n_loc] = fmaxf(y0.z * sSc[k0 + 2] + sSh[k0 + 2], 0.f);
        sA[(k0 + 3) * 32 + n_loc] = fmaxf(y0.w * sSc[k0 + 3] + sSh[k0 + 3], 0.f);
        sA[(k0 + 4) * 32 + n_loc] = fmaxf(y1v.x * sSc[k0 + 4] + sSh[k0 + 4], 0.f);
        sA[(k0 + 5) * 32 + n_loc] = fmaxf(y1v.y * sSc[k0 + 5] + sSh[k0 + 5], 0.f);
        sA[(k0 + 6) * 32 + n_loc] = fmaxf(y1v.z * sSc[k0 + 6] + sSh[k0 + 6], 0.f);
        sA[(k0 + 7) * 32 + n_loc] = fmaxf(y1v.w * sSc[k0 + 7] + sSh[k0 + 7], 0.f);
    }
    __syncthreads();

    int tx = t & 63, ty = t >> 6;
    unsigned long long acc[4] = {0ull, 0ull, 0ull, 0ull};
#pragma unroll 8
    for (int k = 0; k < 64; k++) {
        float w = sW[k * 64 + tx];
        unsigned long long w2 = pack2(w, w);
        const ulonglong2* ap = (const ulonglong2*)(sA + k * 32 + ty * 8);
        ulonglong2 a01 = ap[0];
        ulonglong2 a23 = ap[1];
        ffma2(acc[0], a01.x, w2);
        ffma2(acc[1], a01.y, w2);
        ffma2(acc[2], a23.x, w2);
        ffma2(acc[3], a23.y, w2);
    }
    float bb = bias[l * 64 + tx];
    float s = 0.f, q = 0.f;
#pragma unroll
    for (int p = 0; p < 4; p++) {
        float2 v = unpack2(acc[p]);
        int na = ty * 8 + p * 2;
        float yA = v.x + bb, yB = v.y + bb;
        g_y2[(size_t)(n0 + na) * 64 + tx] = yA;
        g_y2[(size_t)(n0 + na + 1) * 64 + tx] = yB;
        s += yA + yB;
        q += yA * yA + yB * yB;
    }
    sRs[t] = s;
    sRq[t] = q;
    __syncthreads();
    if (t < 64) {
        s = sRs[t] + sRs[64 + t] + sRs[128 + t] + sRs[192 + t];
        q = sRq[t] + sRq[64 + t] + sRq[128 + t] + sRq[192 + t];
        atomicAdd(&g_stats[128 + t], s);
        atomicAdd(&g_stats[192 + t], q);
    }
}

// x_out = BN2(y2) [+ relu unless last layer]
__global__ void bn_apply_kernel(const float* __restrict__ bg, const float* __restrict__ bnb,
                                float* __restrict__ xout, int l, int do_relu) {
    int i = blockIdx.x * 256 + threadIdx.x;   // < N*64
    int h = i & 63;
    float mu = g_stats[128 + h] * (1.0f / NN);
    float var = g_stats[192 + h] * (1.0f / NN) - mu * mu;
    float rs = rsqrtf(var + EPS_BN);
    float sc = rs * bg[l * 64 + h];
    float sh = bnb[l * 64 + h] - mu * sc;
    float v = g_y2[i] * sc + sh;
    if (do_relu) v = fmaxf(v, 0.f);
    xout[i] = v;
}

// ---------------- launcher ----------------
extern "C" void kernel_launch(void* const* d_in, const int* in_sizes, int n_in,
                              void* d_out, int out_size) {
    const float* x        = (const float*)d_in[0];
    const float* pe       = (const float*)d_in[1];
    const float* Lam      = (const float*)d_in[2];
    const float* edge_attr= (const float*)d_in[3];
    const float* pw1      = (const float*)d_in[4];
    const float* pb1      = (const float*)d_in[5];
    const float* pw2      = (const float*)d_in[6];
    const float* pb2      = (const float*)d_in[7];
    const float* enc_w    = (const float*)d_in[8];
    const float* enc_b    = (const float*)d_in[9];
    const float* lin_w    = (const float*)d_in[10];
    const float* lin_b    = (const float*)d_in[11];
    const float* mw1      = (const float*)d_in[12];
    const float* mb1      = (const float*)d_in[13];
    const float* bn1g     = (const float*)d_in[14];
    const float* bn1b     = (const float*)d_in[15];
    const float* mw2      = (const float*)d_in[16];
    const float* mb2      = (const float*)d_in[17];
    const float* bn2g     = (const float*)d_in[18];
    const float* bn2b     = (const float*)d_in[19];
    const int*   ei       = (const int*)d_in[20];
    const int*   batch    = (const int*)d_in[21];
    float* out = (float*)d_out;

    float* xb = nullptr;
    cudaGetSymbolAddress((void**)&xb, g_xb);

    // pe passthrough into second half of the output
    if (out_size >= (int)(2u * NN * 64)) {
        copy_pe_kernel<<<NN * 16 / 256, 256>>>(pe, out + (size_t)NN * 64);
    }
    // layer-invariant complex edge features + edge graph ids
    z_kernel<<<EE / 8, 256>>>(pe, ei, batch);
    // CSR by dst (layer-invariant)
    deg_zero_kernel<<<(NN + 255) / 256, 256>>>();
    deg_count_kernel<<<EE / 256, 256>>>(ei);
    scan_kernel<<<1, 1024>>>();
    fill_kernel<<<EE / 256, 256>>>(ei);

    for (int l = 0; l < LL; l++) {
        const float* xcur = (l == 0) ? x : (const float*)xb;
        float* xout = (l == LL - 1) ? out : xb;
        phi_kernel<<<(BB * QMM + 255) / 256, 256>>>(Lam, pw1, pb1, pw2, pb2, l);
        fuse_kernel<<<64, 64>>>(enc_w, enc_b, lin_w, lin_b, l);
        edge_kernel<<<EE / 64, 256>>>(edge_attr, xcur, ei);
        nodeA_kernel<<<NN / 32, 256>>>(xcur, mw1, mb1, l);
        nodeB_kernel<<<NN / 32, 256>>>(mw2, mb2, bn1g, bn1b, l);
        bn_apply_kernel<<<NN * 64 / 256, 256>>>(bn2g, bn2b, xout, l, (l != LL - 1) ? 1 : 0);
    }
}

// round 6
// speedup vs baseline: 1.1215x; 1.1215x over previous
#include <cuda_runtime.h>
#include <cstdint>

#define NN 100000
#define EE 800000
#define HH 64
#define QMM 32
#define BB 100
#define LL 4
#define EPS_BN 1e-5f

// ---------------- scratch (static __device__ — no allocations allowed) ----------------
__device__ float g_feat[(size_t)EE * 64];   // [z_re(32) | z_im(32)] per edge, 204.8 MB
__device__ int   g_eg[EE];                  // graph id per edge
__device__ float g_agg[(size_t)NN * 64];    // edge aggregation (atomic)
__device__ float g_y1[(size_t)NN * 64];     // pre-BN1 activations
__device__ float g_y2[(size_t)NN * 64];     // pre-BN2 activations
__device__ float g_xb[(size_t)NN * 64];     // node feature ping buffer
__device__ float g_wtab[BB * QMM];          // per-graph eigen weights w[B,Q*M]
__device__ float g_Wc[128 * 64];            // fused edge weight [W1;W2]
__device__ float g_bc[64];                  // fused edge bias
__device__ float g_stats[256];              // [bn1 sum | bn1 sq | bn2 sum | bn2 sq]

// ---------------- f32x2 packed math helpers (Blackwell) ----------------
__device__ __forceinline__ unsigned long long pack2(float a, float b) {
    unsigned long long r;
    asm("mov.b64 %0, {%1, %2};" : "=l"(r) : "f"(a), "f"(b));
    return r;
}
__device__ __forceinline__ void ffma2(unsigned long long& d, unsigned long long a, unsigned long long b) {
    asm("fma.rn.f32x2 %0, %1, %2, %0;" : "+l"(d) : "l"(a), "l"(b));
}
__device__ __forceinline__ float2 unpack2(unsigned long long v) {
    float2 r;
    asm("mov.b64 {%0, %1}, %2;" : "=f"(r.x), "=f"(r.y) : "l"(v));
    return r;
}

// ---------------- one-time precompute ----------------

// z = pe[src] * conj(pe[dst]); one warp per edge, lane = (q,m)
__global__ __launch_bounds__(256) void z_kernel(const float* __restrict__ pe,
                                                const int* __restrict__ ei,
                                                const int* __restrict__ batch) {
    int e = blockIdx.x * 8 + (threadIdx.x >> 5);
    int qm = threadIdx.x & 31;
    int src = ei[e];
    int dst = ei[EE + e];
    const float2* pe2 = (const float2*)pe;
    float2 zs = pe2[(size_t)src * 32 + qm];
    float2 zd = pe2[(size_t)dst * 32 + qm];
    float zr = zs.x * zd.x + zs.y * zd.y;
    float zi = zs.y * zd.x - zs.x * zd.y;
    g_feat[(size_t)e * 64 + qm] = zr;
    g_feat[(size_t)e * 64 + 32 + qm] = zi;
    if (qm == 0) g_eg[e] = batch[src];
}

__global__ void copy_pe_kernel(const float* __restrict__ pe, float* __restrict__ out) {
    size_t i = (size_t)blockIdx.x * 256 + threadIdx.x;   // < N*16 float4
    ((float4*)out)[i] = ((const float4*)pe)[i];
}

// ---------------- per-layer prep: zero agg+stats, phi MLP, weight fusion ----------------
// grid = NN*16/256 = 6250 blocks of 256 threads.
//   every block: zero a slice of g_agg
//   block 0:     zero g_stats
//   blocks 0-63: fuse row k=blockIdx.x (threads 0-63)
//   blocks 64-76: phi for 3200 (b,qm) entries
__global__ void prep_kernel(const float* __restrict__ Lam, const float* __restrict__ pw1,
                            const float* __restrict__ pb1, const float* __restrict__ pw2,
                            const float* __restrict__ pb2,
                            const float* __restrict__ enc_w, const float* __restrict__ enc_b,
                            const float* __restrict__ lin_w, const float* __restrict__ lin_b,
                            int l) {
    size_t i = (size_t)blockIdx.x * 256 + threadIdx.x;
    ((float4*)g_agg)[i] = make_float4(0.f, 0.f, 0.f, 0.f);
    int b = blockIdx.x, t = threadIdx.x;
    if (b == 0) g_stats[t] = 0.f;
    if (b < 64 && t < 64) {
        int k = b, h = t;
        const float* ew = enc_w + (size_t)l * 64 * 64;
        const float* lw = lin_w + (size_t)l * 64 * 64;
        float s = 0.f;
        for (int j = 0; j < 64; j++) s += ew[k * 64 + j] * lw[j * 64 + h];
        g_Wc[k * 64 + h] = s;
        g_Wc[(64 + k) * 64 + h] = lw[k * 64 + h];
        if (k == 0) {
            float bias = lin_b[l * 64 + h];
            for (int j = 0; j < 64; j++) bias += enc_b[l * 64 + j] * lw[j * 64 + h];
            g_bc[h] = bias;
        }
    } else if (b >= 64 && b < 77) {
        int idx = (b - 64) * 256 + t;
        if (idx < BB * QMM) {
            float lam = Lam[idx];
            float s = pb2[l];
#pragma unroll
            for (int j = 0; j < 16; j++) {
                float h = fmaxf(lam * pw1[l * 16 + j] + pb1[l * 16 + j], 0.f);
                s += h * pw2[l * 16 + j];
            }
            g_wtab[idx] = s;
        }
    }
}

// ---------------- edge kernel: agg[dst] += relu([feat*we | ea] @ Wc + bc + x[src]) ----
// 64 edges per block, 256 threads, 16 edges per thread (8 f32x2 accumulators).
__global__ __launch_bounds__(256) void edge_kernel(const float* __restrict__ edge_attr,
                                                   const float* __restrict__ xcur,
                                                   const int* __restrict__ ei) {
    __shared__ float sW[64 * 64];    // 16 KB, per-phase W
    __shared__ float sA[64 * 64];    // 16 KB, k-major [k][edge]
    __shared__ int sSrc[64], sDst[64], sG[64];
    __shared__ float sB[64];
    int t = threadIdx.x;
    int e0 = blockIdx.x * 64;
    int e_loc = t & 63, part = t >> 6;   // 64 edges x 4 k-chunks(16)
    int e = e0 + e_loc;
    int k0 = part * 16;

    // phase-1 W (rows 0..63) + per-edge metadata
    {
        const float4* Wv = (const float4*)g_Wc;
        float4* sWv = (float4*)sW;
#pragma unroll
        for (int i = 0; i < 4; i++) sWv[t + 256 * i] = Wv[t + 256 * i];
    }
    if (t < 64) {
        sSrc[t] = ei[e0 + t];
        sDst[t] = ei[EE + e0 + t];
        sG[t] = g_eg[e0 + t];
        sB[t] = g_bc[t];
    }
    __syncthreads();   // sG visible for staging

    // phase-1 staging: feat * we (k = 0..63)
    {
        const float* wv = g_wtab + sG[e_loc] * QMM;
        int m0 = k0 & 31;
#pragma unroll
        for (int c = 0; c < 4; c++) {
            float4 f = *(const float4*)(g_feat + (size_t)e * 64 + k0 + c * 4);
            sA[(k0 + c * 4 + 0) * 64 + e_loc] = f.x * wv[m0 + c * 4 + 0];
            sA[(k0 + c * 4 + 1) * 64 + e_loc] = f.y * wv[m0 + c * 4 + 1];
            sA[(k0 + c * 4 + 2) * 64 + e_loc] = f.z * wv[m0 + c * 4 + 2];
            sA[(k0 + c * 4 + 3) * 64 + e_loc] = f.w * wv[m0 + c * 4 + 3];
        }
    }
    // prefetch edge_attr (k=64..127 inputs) into registers — overlaps with phase-1 math
    float4 ea0 = *(const float4*)(edge_attr + (size_t)e * 64 + k0);
    float4 ea1 = *(const float4*)(edge_attr + (size_t)e * 64 + k0 + 4);
    float4 ea2 = *(const float4*)(edge_attr + (size_t)e * 64 + k0 + 8);
    float4 ea3 = *(const float4*)(edge_attr + (size_t)e * 64 + k0 + 12);
    __syncthreads();

    int tx = t & 63, ty = t >> 6;   // channel, edge-16-group
    unsigned long long acc[8] = {0ull,0ull,0ull,0ull,0ull,0ull,0ull,0ull};
#pragma unroll 8
    for (int k = 0; k < 64; k++) {
        float w = sW[k * 64 + tx];
        unsigned long long w2 = pack2(w, w);
        const ulonglong2* ap = (const ulonglong2*)(sA + k * 64 + ty * 16);
        ulonglong2 a01 = ap[0], a23 = ap[1], a45 = ap[2], a67 = ap[3];
        ffma2(acc[0], a01.x, w2);
        ffma2(acc[1], a01.y, w2);
        ffma2(acc[2], a23.x, w2);
        ffma2(acc[3], a23.y, w2);
        ffma2(acc[4], a45.x, w2);
        ffma2(acc[5], a45.y, w2);
        ffma2(acc[6], a67.x, w2);
        ffma2(acc[7], a67.y, w2);
    }
    __syncthreads();

    // phase-2: W rows 64..127 + edge_attr staging (from registers)
    {
        const float4* Wv = (const float4*)(g_Wc + 64 * 64);
        float4* sWv = (float4*)sW;
#pragma unroll
        for (int i = 0; i < 4; i++) sWv[t + 256 * i] = Wv[t + 256 * i];
    }
    sA[(k0 + 0) * 64 + e_loc] = ea0.x;
    sA[(k0 + 1) * 64 + e_loc] = ea0.y;
    sA[(k0 + 2) * 64 + e_loc] = ea0.z;
    sA[(k0 + 3) * 64 + e_loc] = ea0.w;
    sA[(k0 + 4) * 64 + e_loc] = ea1.x;
    sA[(k0 + 5) * 64 + e_loc] = ea1.y;
    sA[(k0 + 6) * 64 + e_loc] = ea1.z;
    sA[(k0 + 7) * 64 + e_loc] = ea1.w;
    sA[(k0 + 8) * 64 + e_loc] = ea2.x;
    sA[(k0 + 9) * 64 + e_loc] = ea2.y;
    sA[(k0 + 10) * 64 + e_loc] = ea2.z;
    sA[(k0 + 11) * 64 + e_loc] = ea2.w;
    sA[(k0 + 12) * 64 + e_loc] = ea3.x;
    sA[(k0 + 13) * 64 + e_loc] = ea3.y;
    sA[(k0 + 14) * 64 + e_loc] = ea3.z;
    sA[(k0 + 15) * 64 + e_loc] = ea3.w;
    __syncthreads();
#pragma unroll 8
    for (int k = 0; k < 64; k++) {
        float w = sW[k * 64 + tx];
        unsigned long long w2 = pack2(w, w);
        const ulonglong2* ap = (const ulonglong2*)(sA + k * 64 + ty * 16);
        ulonglong2 a01 = ap[0], a23 = ap[1], a45 = ap[2], a67 = ap[3];
        ffma2(acc[0], a01.x, w2);
        ffma2(acc[1], a01.y, w2);
        ffma2(acc[2], a23.x, w2);
        ffma2(acc[3], a23.y, w2);
        ffma2(acc[4], a45.x, w2);
        ffma2(acc[5], a45.y, w2);
        ffma2(acc[6], a67.x, w2);
        ffma2(acc[7], a67.y, w2);
    }

    float b = sB[tx];
#pragma unroll
    for (int p = 0; p < 8; p++) {
        float2 v = unpack2(acc[p]);
        int ea = ty * 16 + p * 2;
        float vA = fmaxf(v.x + b + xcur[(size_t)sSrc[ea] * 64 + tx], 0.f);
        float vB = fmaxf(v.y + b + xcur[(size_t)sSrc[ea + 1] * 64 + tx], 0.f);
        atomicAdd(&g_agg[(size_t)sDst[ea] * 64 + tx], vA);
        atomicAdd(&g_agg[(size_t)sDst[ea + 1] * 64 + tx], vB);
    }
}

// ---------------- node kernels ----------------

// y1 = (x + agg) @ mlp_w1 + b1 ; accumulate BN1 column stats
__global__ __launch_bounds__(256) void nodeA_kernel(const float* __restrict__ xcur,
                                                    const float* __restrict__ W,
                                                    const float* __restrict__ bias, int l) {
    __shared__ float sW[64 * 64];
    __shared__ float sA[64 * 32];
    __shared__ float sRs[256], sRq[256];
    int t = threadIdx.x;
    int n0 = blockIdx.x * 32;
    {
        const float4* Wv = (const float4*)(W + (size_t)l * 4096);
        float4* sWv = (float4*)sW;
#pragma unroll
        for (int i = 0; i < 4; i++) sWv[t + 256 * i] = Wv[t + 256 * i];
    }
    int n_loc = t & 31, part = t >> 5;
    int k0 = part * 8;
    {
        size_t base = (size_t)(n0 + n_loc) * 64 + k0;
        float4 x0 = *(const float4*)(xcur + base);
        float4 x1 = *(const float4*)(xcur + base + 4);
        float4 a0 = *(const float4*)(g_agg + base);
        float4 a1 = *(const float4*)(g_agg + base + 4);
        sA[(k0 + 0) * 32 + n_loc] = x0.x + a0.x;
        sA[(k0 + 1) * 32 + n_loc] = x0.y + a0.y;
        sA[(k0 + 2) * 32 + n_loc] = x0.z + a0.z;
        sA[(k0 + 3) * 32 + n_loc] = x0.w + a0.w;
        sA[(k0 + 4) * 32 + n_loc] = x1.x + a1.x;
        sA[(k0 + 5) * 32 + n_loc] = x1.y + a1.y;
        sA[(k0 + 6) * 32 + n_loc] = x1.z + a1.z;
        sA[(k0 + 7) * 32 + n_loc] = x1.w + a1.w;
    }
    __syncthreads();

    int tx = t & 63, ty = t >> 6;
    unsigned long long acc[4] = {0ull, 0ull, 0ull, 0ull};
#pragma unroll 8
    for (int k = 0; k < 64; k++) {
        float w = sW[k * 64 + tx];
        unsigned long long w2 = pack2(w, w);
        const ulonglong2* ap = (const ulonglong2*)(sA + k * 32 + ty * 8);
        ulonglong2 a01 = ap[0];
        ulonglong2 a23 = ap[1];
        ffma2(acc[0], a01.x, w2);
        ffma2(acc[1], a01.y, w2);
        ffma2(acc[2], a23.x, w2);
        ffma2(acc[3], a23.y, w2);
    }
    float bb = bias[l * 64 + tx];
    float s = 0.f, q = 0.f;
#pragma unroll
    for (int p = 0; p < 4; p++) {
        float2 v = unpack2(acc[p]);
        int na = ty * 8 + p * 2;
        float yA = v.x + bb, yB = v.y + bb;
        g_y1[(size_t)(n0 + na) * 64 + tx] = yA;
        g_y1[(size_t)(n0 + na + 1) * 64 + tx] = yB;
        s += yA + yB;
        q += yA * yA + yB * yB;
    }
    sRs[t] = s;
    sRq[t] = q;
    __syncthreads();
    if (t < 64) {
        s = sRs[t] + sRs[64 + t] + sRs[128 + t] + sRs[192 + t];
        q = sRq[t] + sRq[64 + t] + sRq[128 + t] + sRq[192 + t];
        atomicAdd(&g_stats[t], s);
        atomicAdd(&g_stats[64 + t], q);
    }
}

// y2 = relu(BN1(y1)) @ mlp_w2 + b2 ; accumulate BN2 column stats
__global__ __launch_bounds__(256) void nodeB_kernel(const float* __restrict__ W,
                                                    const float* __restrict__ bias,
                                                    const float* __restrict__ bg,
                                                    const float* __restrict__ bnb, int l) {
    __shared__ float sW[64 * 64];
    __shared__ float sA[64 * 32];
    __shared__ float sSc[64], sSh[64];
    __shared__ float sRs[256], sRq[256];
    int t = threadIdx.x;
    int n0 = blockIdx.x * 32;
    {
        const float4* Wv = (const float4*)(W + (size_t)l * 4096);
        float4* sWv = (float4*)sW;
#pragma unroll
        for (int i = 0; i < 4; i++) sWv[t + 256 * i] = Wv[t + 256 * i];
    }
    if (t < 64) {
        float mu = g_stats[t] * (1.0f / NN);
        float var = g_stats[64 + t] * (1.0f / NN) - mu * mu;
        float rs = rsqrtf(var + EPS_BN);
        float sc = rs * bg[l * 64 + t];
        sSc[t] = sc;
        sSh[t] = bnb[l * 64 + t] - mu * sc;
    }
    __syncthreads();
    int n_loc = t & 31, part = t >> 5;
    int k0 = part * 8;
    {
        size_t base = (size_t)(n0 + n_loc) * 64 + k0;
        float4 y0 = *(const float4*)(g_y1 + base);
        float4 y1v = *(const float4*)(g_y1 + base + 4);
        sA[(k0 + 0) * 32 + n_loc] = fmaxf(y0.x * sSc[k0 + 0] + sSh[k0 + 0], 0.f);
        sA[(k0 + 1) * 32 + n_loc] = fmaxf(y0.y * sSc[k0 + 1] + sSh[k0 + 1], 0.f);
        sA[(k0 + 2) * 32 + n_loc] = fmaxf(y0.z * sSc[k0 + 2] + sSh[k0 + 2], 0.f);
        sA[(k0 + 3) * 32 + n_loc] = fmaxf(y0.w * sSc[k0 + 3] + sSh[k0 + 3], 0.f);
        sA[(k0 + 4) * 32 + n_loc] = fmaxf(y1v.x * sSc[k0 + 4] + sSh[k0 + 4], 0.f);
        sA[(k0 + 5) * 32 + n_loc] = fmaxf(y1v.y * sSc[k0 + 5] + sSh[k0 + 5], 0.f);
        sA[(k0 + 6) * 32 + n_loc] = fmaxf(y1v.z * sSc[k0 + 6] + sSh[k0 + 6], 0.f);
        sA[(k0 + 7) * 32 + n_loc] = fmaxf(y1v.w * sSc[k0 + 7] + sSh[k0 + 7], 0.f);
    }
    __syncthreads();

    int tx = t & 63, ty = t >> 6;
    unsigned long long acc[4] = {0ull, 0ull, 0ull, 0ull};
#pragma unroll 8
    for (int k = 0; k < 64; k++) {
        float w = sW[k * 64 + tx];
        unsigned long long w2 = pack2(w, w);
        const ulonglong2* ap = (const ulonglong2*)(sA + k * 32 + ty * 8);
        ulonglong2 a01 = ap[0];
        ulonglong2 a23 = ap[1];
        ffma2(acc[0], a01.x, w2);
        ffma2(acc[1], a01.y, w2);
        ffma2(acc[2], a23.x, w2);
        ffma2(acc[3], a23.y, w2);
    }
    float bb = bias[l * 64 + tx];
    float s = 0.f, q = 0.f;
#pragma unroll
    for (int p = 0; p < 4; p++) {
        float2 v = unpack2(acc[p]);
        int na = ty * 8 + p * 2;
        float yA = v.x + bb, yB = v.y + bb;
        g_y2[(size_t)(n0 + na) * 64 + tx] = yA;
        g_y2[(size_t)(n0 + na + 1) * 64 + tx] = yB;
        s += yA + yB;
        q += yA * yA + yB * yB;
    }
    sRs[t] = s;
    sRq[t] = q;
    __syncthreads();
    if (t < 64) {
        s = sRs[t] + sRs[64 + t] + sRs[128 + t] + sRs[192 + t];
        q = sRq[t] + sRq[64 + t] + sRq[128 + t] + sRq[192 + t];
        atomicAdd(&g_stats[128 + t], s);
        atomicAdd(&g_stats[192 + t], q);
    }
}

// x_out = BN2(y2) [+ relu unless last layer]
__global__ void bn_apply_kernel(const float* __restrict__ bg, const float* __restrict__ bnb,
                                float* __restrict__ xout, int l, int do_relu) {
    int i = blockIdx.x * 256 + threadIdx.x;   // < N*64
    int h = i & 63;
    float mu = g_stats[128 + h] * (1.0f / NN);
    float var = g_stats[192 + h] * (1.0f / NN) - mu * mu;
    float rs = rsqrtf(var + EPS_BN);
    float sc = rs * bg[l * 64 + h];
    float sh = bnb[l * 64 + h] - mu * sc;
    float v = g_y2[i] * sc + sh;
    if (do_relu) v = fmaxf(v, 0.f);
    xout[i] = v;
}

// ---------------- launcher ----------------
extern "C" void kernel_launch(void* const* d_in, const int* in_sizes, int n_in,
                              void* d_out, int out_size) {
    const float* x        = (const float*)d_in[0];
    const float* pe       = (const float*)d_in[1];
    const float* Lam      = (const float*)d_in[2];
    const float* edge_attr= (const float*)d_in[3];
    const float* pw1      = (const float*)d_in[4];
    const float* pb1      = (const float*)d_in[5];
    const float* pw2      = (const float*)d_in[6];
    const float* pb2      = (const float*)d_in[7];
    const float* enc_w    = (const float*)d_in[8];
    const float* enc_b    = (const float*)d_in[9];
    const float* lin_w    = (const float*)d_in[10];
    const float* lin_b    = (const float*)d_in[11];
    const float* mw1      = (const float*)d_in[12];
    const float* mb1      = (const float*)d_in[13];
    const float* bn1g     = (const float*)d_in[14];
    const float* bn1b     = (const float*)d_in[15];
    const float* mw2      = (const float*)d_in[16];
    const float* mb2      = (const float*)d_in[17];
    const float* bn2g     = (const float*)d_in[18];
    const float* bn2b     = (const float*)d_in[19];
    const int*   ei       = (const int*)d_in[20];
    const int*   batch    = (const int*)d_in[21];
    float* out = (float*)d_out;

    float* xb = nullptr;
    cudaGetSymbolAddress((void**)&xb, g_xb);

    // launch #1: pe passthrough into second half of the output
    if (out_size >= (int)(2u * NN * 64)) {
        copy_pe_kernel<<<NN * 16 / 256, 256>>>(pe, out + (size_t)NN * 64);
    }
    // launch #2: layer-invariant complex edge features + edge graph ids
    z_kernel<<<EE / 8, 256>>>(pe, ei, batch);

    for (int l = 0; l < LL; l++) {
        const float* xcur = (l == 0) ? x : (const float*)xb;
        float* xout = (l == LL - 1) ? out : xb;
        // launch #3 (l=0): zero agg/stats + phi + fuse in ONE kernel
        prep_kernel<<<NN * 16 / 256, 256>>>(Lam, pw1, pb1, pw2, pb2,
                                            enc_w, enc_b, lin_w, lin_b, l);
        // launch #4 (l=0): edge kernel — lands in the ncu-profiled slot
        edge_kernel<<<EE / 64, 256>>>(edge_attr, xcur, ei);
        nodeA_kernel<<<NN / 32, 256>>>(xcur, mw1, mb1, l);
        nodeB_kernel<<<NN / 32, 256>>>(mw2, mb2, bn1g, bn1b, l);
        bn_apply_kernel<<<NN * 64 / 256, 256>>>(bn2g, bn2b, xout, l, (l != LL - 1) ? 1 : 0);
    }
}

// round 7
// speedup vs baseline: 1.2461x; 1.1111x over previous
#include <cuda_runtime.h>
#include <cstdint>

#define NN 100000
#define EE 800000
#define HH 64
#define QMM 32
#define BB 100
#define LL 4
#define EPS_BN 1e-5f

// ---------------- scratch (static __device__ — no allocations allowed) ----------------
__device__ float g_feat[(size_t)EE * 64];   // [z_re(32) | z_im(32)] per edge, 204.8 MB
__device__ int   g_eg[EE];                  // graph id per edge
__device__ float g_agg[(size_t)NN * 64];    // edge aggregation (atomic)
__device__ float g_y1[(size_t)NN * 64];     // pre-BN1 activations
__device__ float g_y2[(size_t)NN * 64];     // pre-BN2 activations
__device__ float g_xb[(size_t)NN * 64];     // node feature ping buffer
__device__ float g_wtab[BB * QMM];          // per-graph eigen weights w[B,Q*M]
__device__ float g_Wc[128 * 64];            // fused edge weight [W1;W2]
__device__ float g_bc[64];                  // fused edge bias
__device__ float g_stats[256];              // [bn1 sum | bn1 sq | bn2 sum | bn2 sq]

// ---------------- f32x2 packed math helpers (Blackwell) ----------------
__device__ __forceinline__ unsigned long long pack2(float a, float b) {
    unsigned long long r;
    asm("mov.b64 %0, {%1, %2};" : "=l"(r) : "f"(a), "f"(b));
    return r;
}
__device__ __forceinline__ void ffma2(unsigned long long& d, unsigned long long a, unsigned long long b) {
    asm("fma.rn.f32x2 %0, %1, %2, %0;" : "+l"(d) : "l"(a), "l"(b));
}
__device__ __forceinline__ float2 unpack2(unsigned long long v) {
    float2 r;
    asm("mov.b64 {%0, %1}, %2;" : "=f"(r.x), "=f"(r.y) : "l"(v));
    return r;
}
__device__ __forceinline__ void red_add_v4(float* p, float a, float b, float c, float d) {
    asm volatile("red.global.add.v4.f32 [%0], {%1, %2, %3, %4};"
                 :: "l"(p), "f"(a), "f"(b), "f"(c), "f"(d) : "memory");
}

// ---------------- one-time precompute ----------------

// z = pe[src] * conj(pe[dst]); one warp per edge, lane = (q,m)
__global__ __launch_bounds__(256) void z_kernel(const float* __restrict__ pe,
                                                const int* __restrict__ ei,
                                                const int* __restrict__ batch) {
    int e = blockIdx.x * 8 + (threadIdx.x >> 5);
    int qm = threadIdx.x & 31;
    int src = ei[e];
    int dst = ei[EE + e];
    const float2* pe2 = (const float2*)pe;
    float2 zs = pe2[(size_t)src * 32 + qm];
    float2 zd = pe2[(size_t)dst * 32 + qm];
    float zr = zs.x * zd.x + zs.y * zd.y;
    float zi = zs.y * zd.x - zs.x * zd.y;
    g_feat[(size_t)e * 64 + qm] = zr;
    g_feat[(size_t)e * 64 + 32 + qm] = zi;
    if (qm == 0) g_eg[e] = batch[src];
}

__global__ void copy_pe_kernel(const float* __restrict__ pe, float* __restrict__ out) {
    size_t i = (size_t)blockIdx.x * 256 + threadIdx.x;   // < N*16 float4
    ((float4*)out)[i] = ((const float4*)pe)[i];
}

// ---------------- per-layer prep: zero agg+stats, phi MLP, weight fusion ----------------
__global__ void prep_kernel(const float* __restrict__ Lam, const float* __restrict__ pw1,
                            const float* __restrict__ pb1, const float* __restrict__ pw2,
                            const float* __restrict__ pb2,
                            const float* __restrict__ enc_w, const float* __restrict__ enc_b,
                            const float* __restrict__ lin_w, const float* __restrict__ lin_b,
                            int l) {
    size_t i = (size_t)blockIdx.x * 256 + threadIdx.x;
    ((float4*)g_agg)[i] = make_float4(0.f, 0.f, 0.f, 0.f);
    int b = blockIdx.x, t = threadIdx.x;
    if (b == 0) g_stats[t] = 0.f;
    if (b < 64 && t < 64) {
        int k = b, h = t;
        const float* ew = enc_w + (size_t)l * 64 * 64;
        const float* lw = lin_w + (size_t)l * 64 * 64;
        float s = 0.f;
        for (int j = 0; j < 64; j++) s += ew[k * 64 + j] * lw[j * 64 + h];
        g_Wc[k * 64 + h] = s;
        g_Wc[(64 + k) * 64 + h] = lw[k * 64 + h];
        if (k == 0) {
            float bias = lin_b[l * 64 + h];
            for (int j = 0; j < 64; j++) bias += enc_b[l * 64 + j] * lw[j * 64 + h];
            g_bc[h] = bias;
        }
    } else if (b >= 64 && b < 77) {
        int idx = (b - 64) * 256 + t;
        if (idx < BB * QMM) {
            float lam = Lam[idx];
            float s = pb2[l];
#pragma unroll
            for (int j = 0; j < 16; j++) {
                float h = fmaxf(lam * pw1[l * 16 + j] + pb1[l * 16 + j], 0.f);
                s += h * pw2[l * 16 + j];
            }
            g_wtab[idx] = s;
        }
    }
}

// ---------------- edge kernel: agg[dst] += relu([feat*we | ea] @ Wc + bc + x[src]) ----
// 256 edges per block, 256 threads; thread owns 8 edges x 8 channels (8x8 reg tile).
// K=128 in 4 phases of 32. LSU and FMA pipes balanced (~128 cyc/CTA/k each).
__global__ __launch_bounds__(256) void edge_kernel(const float* __restrict__ edge_attr,
                                                   const float* __restrict__ xcur,
                                                   const int* __restrict__ ei) {
    __shared__ float sW[32 * 64];     // 8 KB  : W rows for this phase
    __shared__ float sA[32 * 256];    // 32 KB : A k-major [k][edge]
    __shared__ int sSrc[256], sDst[256];
    int t = threadIdx.x;
    int e0 = blockIdx.x * 256;
    int eg8 = (t & 31) * 8;   // edge offset within tile
    int c8 = (t >> 5) * 8;    // channel offset

    sSrc[t] = ei[e0 + t];
    sDst[t] = ei[EE + e0 + t];
    const float* wv = g_wtab + g_eg[e0 + t] * QMM;

    unsigned long long acc[4][8];
#pragma unroll
    for (int p = 0; p < 4; p++)
#pragma unroll
        for (int j = 0; j < 8; j++) acc[p][j] = 0ull;

    for (int ph = 0; ph < 4; ph++) {
        if (ph) __syncthreads();   // protect previous phase's sA/sW reads
        // stage W rows [ph*32, ph*32+32)
        {
            const float4* Wv = (const float4*)(g_Wc + ph * 32 * 64);
            ((float4*)sW)[t] = Wv[t];
            ((float4*)sW)[t + 256] = Wv[t + 256];
        }
        // stage A: thread t stages its own edge's 32-k chunk
        if (ph < 2) {
            const float4* src = (const float4*)(g_feat + (size_t)(e0 + t) * 64 + ph * 32);
#pragma unroll
            for (int q = 0; q < 8; q++) {
                float4 f = src[q];
                sA[(q * 4 + 0) * 256 + t] = f.x * wv[q * 4 + 0];
                sA[(q * 4 + 1) * 256 + t] = f.y * wv[q * 4 + 1];
                sA[(q * 4 + 2) * 256 + t] = f.z * wv[q * 4 + 2];
                sA[(q * 4 + 3) * 256 + t] = f.w * wv[q * 4 + 3];
            }
        } else {
            const float4* src = (const float4*)(edge_attr + (size_t)(e0 + t) * 64 + (ph - 2) * 32);
#pragma unroll
            for (int q = 0; q < 8; q++) {
                float4 f = src[q];
                sA[(q * 4 + 0) * 256 + t] = f.x;
                sA[(q * 4 + 1) * 256 + t] = f.y;
                sA[(q * 4 + 2) * 256 + t] = f.z;
                sA[(q * 4 + 3) * 256 + t] = f.w;
            }
        }
        __syncthreads();

#pragma unroll 2
        for (int k = 0; k < 32; k++) {
            const float4* wrow = (const float4*)(sW + k * 64 + c8);
            float4 w0 = wrow[0], w1 = wrow[1];
            unsigned long long W2[8];
            W2[0] = pack2(w0.x, w0.x);
            W2[1] = pack2(w0.y, w0.y);
            W2[2] = pack2(w0.z, w0.z);
            W2[3] = pack2(w0.w, w0.w);
            W2[4] = pack2(w1.x, w1.x);
            W2[5] = pack2(w1.y, w1.y);
            W2[6] = pack2(w1.z, w1.z);
            W2[7] = pack2(w1.w, w1.w);
            const ulonglong2* ar = (const ulonglong2*)(sA + k * 256 + eg8);
            ulonglong2 aA = ar[0];   // edges (0,1),(2,3)
            ulonglong2 aB = ar[1];   // edges (4,5),(6,7)
#pragma unroll
            for (int j = 0; j < 8; j++) {
                ffma2(acc[0][j], aA.x, W2[j]);
                ffma2(acc[1][j], aA.y, W2[j]);
                ffma2(acc[2][j], aB.x, W2[j]);
                ffma2(acc[3][j], aB.y, W2[j]);
            }
        }
    }

    // epilogue: + bias + x[src], relu, vector-atomic scatter to agg[dst]
    float bias8[8];
#pragma unroll
    for (int j = 0; j < 8; j++) bias8[j] = g_bc[c8 + j];

#pragma unroll
    for (int p = 0; p < 4; p++) {
#pragma unroll
        for (int h = 0; h < 2; h++) {
            int el = eg8 + p * 2 + h;
            int srcn = sSrc[el], dstn = sDst[el];
            const float* xr = xcur + (size_t)srcn * 64 + c8;
            float4 x0 = *(const float4*)xr;
            float4 x1 = *(const float4*)(xr + 4);
            float v[8];
#pragma unroll
            for (int j = 0; j < 8; j++) {
                float2 u = unpack2(acc[p][j]);
                v[j] = h ? u.y : u.x;
            }
            v[0] = fmaxf(v[0] + bias8[0] + x0.x, 0.f);
            v[1] = fmaxf(v[1] + bias8[1] + x0.y, 0.f);
            v[2] = fmaxf(v[2] + bias8[2] + x0.z, 0.f);
            v[3] = fmaxf(v[3] + bias8[3] + x0.w, 0.f);
            v[4] = fmaxf(v[4] + bias8[4] + x1.x, 0.f);
            v[5] = fmaxf(v[5] + bias8[5] + x1.y, 0.f);
            v[6] = fmaxf(v[6] + bias8[6] + x1.z, 0.f);
            v[7] = fmaxf(v[7] + bias8[7] + x1.w, 0.f);
            float* dp = g_agg + (size_t)dstn * 64 + c8;
            red_add_v4(dp, v[0], v[1], v[2], v[3]);
            red_add_v4(dp + 4, v[4], v[5], v[6], v[7]);
        }
    }
}

// ---------------- node kernels ----------------

// y1 = (x + agg) @ mlp_w1 + b1 ; accumulate BN1 column stats
__global__ __launch_bounds__(256) void nodeA_kernel(const float* __restrict__ xcur,
                                                    const float* __restrict__ W,
                                                    const float* __restrict__ bias, int l) {
    __shared__ float sW[64 * 64];
    __shared__ float sA[64 * 32];
    __shared__ float sRs[256], sRq[256];
    int t = threadIdx.x;
    int n0 = blockIdx.x * 32;
    {
        const float4* Wv = (const float4*)(W + (size_t)l * 4096);
        float4* sWv = (float4*)sW;
#pragma unroll
        for (int i = 0; i < 4; i++) sWv[t + 256 * i] = Wv[t + 256 * i];
    }
    int n_loc = t & 31, part = t >> 5;
    int k0 = part * 8;
    {
        size_t base = (size_t)(n0 + n_loc) * 64 + k0;
        float4 x0 = *(const float4*)(xcur + base);
        float4 x1 = *(const float4*)(xcur + base + 4);
        float4 a0 = *(const float4*)(g_agg + base);
        float4 a1 = *(const float4*)(g_agg + base + 4);
        sA[(k0 + 0) * 32 + n_loc] = x0.x + a0.x;
        sA[(k0 + 1) * 32 + n_loc] = x0.y + a0.y;
        sA[(k0 + 2) * 32 + n_loc] = x0.z + a0.z;
        sA[(k0 + 3) * 32 + n_loc] = x0.w + a0.w;
        sA[(k0 + 4) * 32 + n_loc] = x1.x + a1.x;
        sA[(k0 + 5) * 32 + n_loc] = x1.y + a1.y;
        sA[(k0 + 6) * 32 + n_loc] = x1.z + a1.z;
        sA[(k0 + 7) * 32 + n_loc] = x1.w + a1.w;
    }
    __syncthreads();

    int tx = t & 63, ty = t >> 6;
    unsigned long long acc[4] = {0ull, 0ull, 0ull, 0ull};
#pragma unroll 8
    for (int k = 0; k < 64; k++) {
        float w = sW[k * 64 + tx];
        unsigned long long w2 = pack2(w, w);
        const ulonglong2* ap = (const ulonglong2*)(sA + k * 32 + ty * 8);
        ulonglong2 a01 = ap[0];
        ulonglong2 a23 = ap[1];
        ffma2(acc[0], a01.x, w2);
        ffma2(acc[1], a01.y, w2);
        ffma2(acc[2], a23.x, w2);
        ffma2(acc[3], a23.y, w2);
    }
    float bb = bias[l * 64 + tx];
    float s = 0.f, q = 0.f;
#pragma unroll
    for (int p = 0; p < 4; p++) {
        float2 v = unpack2(acc[p]);
        int na = ty * 8 + p * 2;
        float yA = v.x + bb, yB = v.y + bb;
        g_y1[(size_t)(n0 + na) * 64 + tx] = yA;
        g_y1[(size_t)(n0 + na + 1) * 64 + tx] = yB;
        s += yA + yB;
        q += yA * yA + yB * yB;
    }
    sRs[t] = s;
    sRq[t] = q;
    __syncthreads();
    if (t < 64) {
        s = sRs[t] + sRs[64 + t] + sRs[128 + t] + sRs[192 + t];
        q = sRq[t] + sRq[64 + t] + sRq[128 + t] + sRq[192 + t];
        atomicAdd(&g_stats[t], s);
        atomicAdd(&g_stats[64 + t], q);
    }
}

// y2 = relu(BN1(y1)) @ mlp_w2 + b2 ; accumulate BN2 column stats
__global__ __launch_bounds__(256) void nodeB_kernel(const float* __restrict__ W,
                                                    const float* __restrict__ bias,
                                                    const float* __restrict__ bg,
                                                    const float* __restrict__ bnb, int l) {
    __shared__ float sW[64 * 64];
    __shared__ float sA[64 * 32];
    __shared__ float sSc[64], sSh[64];
    __shared__ float sRs[256], sRq[256];
    int t = threadIdx.x;
    int n0 = blockIdx.x * 32;
    {
        const float4* Wv = (const float4*)(W + (size_t)l * 4096);
        float4* sWv = (float4*)sW;
#pragma unroll
        for (int i = 0; i < 4; i++) sWv[t + 256 * i] = Wv[t + 256 * i];
    }
    if (t < 64) {
        float mu = g_stats[t] * (1.0f / NN);
        float var = g_stats[64 + t] * (1.0f / NN) - mu * mu;
        float rs = rsqrtf(var + EPS_BN);
        float sc = rs * bg[l * 64 + t];
        sSc[t] = sc;
        sSh[t] = bnb[l * 64 + t] - mu * sc;
    }
    __syncthreads();
    int n_loc = t & 31, part = t >> 5;
    int k0 = part * 8;
    {
        size_t base = (size_t)(n0 + n_loc) * 64 + k0;
        float4 y0 = *(const float4*)(g_y1 + base);
        float4 y1v = *(const float4*)(g_y1 + base + 4);
        sA[(k0 + 0) * 32 + n_loc] = fmaxf(y0.x * sSc[k0 + 0] + sSh[k0 + 0], 0.f);
        sA[(k0 + 1) * 32 + n_loc] = fmaxf(y0.y * sSc[k0 + 1] + sSh[k0 + 1], 0.f);
        sA[(k0 + 2) * 32 + n_loc] = fmaxf(y0.z * sSc[k0 + 2] + sSh[k0 + 2], 0.f);
        sA[(k0 + 3) * 32 + n_loc] = fmaxf(y0.w * sSc[k0 + 3] + sSh[k0 + 3], 0.f);
        sA[(k0 + 4) * 32 + n_loc] = fmaxf(y1v.x * sSc[k0 + 4] + sSh[k0 + 4], 0.f);
        sA[(k0 + 5) * 32 + n_loc] = fmaxf(y1v.y * sSc[k0 + 5] + sSh[k0 + 5], 0.f);
        sA[(k0 + 6) * 32 + n_loc] = fmaxf(y1v.z * sSc[k0 + 6] + sSh[k0 + 6], 0.f);
        sA[(k0 + 7) * 32 + n_loc] = fmaxf(y1v.w * sSc[k0 + 7] + sSh[k0 + 7], 0.f);
    }
    __syncthreads();

    int tx = t & 63, ty = t >> 6;
    unsigned long long acc[4] = {0ull, 0ull, 0ull, 0ull};
#pragma unroll 8
    for (int k = 0; k < 64; k++) {
        float w = sW[k * 64 + tx];
        unsigned long long w2 = pack2(w, w);
        const ulonglong2* ap = (const ulonglong2*)(sA + k * 32 + ty * 8);
        ulonglong2 a01 = ap[0];
        ulonglong2 a23 = ap[1];
        ffma2(acc[0], a01.x, w2);
        ffma2(acc[1], a01.y, w2);
        ffma2(acc[2], a23.x, w2);
        ffma2(acc[3], a23.y, w2);
    }
    float bb = bias[l * 64 + tx];
    float s = 0.f, q = 0.f;
#pragma unroll
    for (int p = 0; p < 4; p++) {
        float2 v = unpack2(acc[p]);
        int na = ty * 8 + p * 2;
        float yA = v.x + bb, yB = v.y + bb;
        g_y2[(size_t)(n0 + na) * 64 + tx] = yA;
        g_y2[(size_t)(n0 + na + 1) * 64 + tx] = yB;
        s += yA + yB;
        q += yA * yA + yB * yB;
    }
    sRs[t] = s;
    sRq[t] = q;
    __syncthreads();
    if (t < 64) {
        s = sRs[t] + sRs[64 + t] + sRs[128 + t] + sRs[192 + t];
        q = sRq[t] + sRq[64 + t] + sRq[128 + t] + sRq[192 + t];
        atomicAdd(&g_stats[128 + t], s);
        atomicAdd(&g_stats[192 + t], q);
    }
}

// x_out = BN2(y2) [+ relu unless last layer]
__global__ void bn_apply_kernel(const float* __restrict__ bg, const float* __restrict__ bnb,
                                float* __restrict__ xout, int l, int do_relu) {
    int i = blockIdx.x * 256 + threadIdx.x;   // < N*64
    int h = i & 63;
    float mu = g_stats[128 + h] * (1.0f / NN);
    float var = g_stats[192 + h] * (1.0f / NN) - mu * mu;
    float rs = rsqrtf(var + EPS_BN);
    float sc = rs * bg[l * 64 + h];
    float sh = bnb[l * 64 + h] - mu * sc;
    float v = g_y2[i] * sc + sh;
    if (do_relu) v = fmaxf(v, 0.f);
    xout[i] = v;
}

// ---------------- launcher ----------------
extern "C" void kernel_launch(void* const* d_in, const int* in_sizes, int n_in,
                              void* d_out, int out_size) {
    const float* x        = (const float*)d_in[0];
    const float* pe       = (const float*)d_in[1];
    const float* Lam      = (const float*)d_in[2];
    const float* edge_attr= (const float*)d_in[3];
    const float* pw1      = (const float*)d_in[4];
    const float* pb1      = (const float*)d_in[5];
    const float* pw2      = (const float*)d_in[6];
    const float* pb2      = (const float*)d_in[7];
    const float* enc_w    = (const float*)d_in[8];
    const float* enc_b    = (const float*)d_in[9];
    const float* lin_w    = (const float*)d_in[10];
    const float* lin_b    = (const float*)d_in[11];
    const float* mw1      = (const float*)d_in[12];
    const float* mb1      = (const float*)d_in[13];
    const float* bn1g     = (const float*)d_in[14];
    const float* bn1b     = (const float*)d_in[15];
    const float* mw2      = (const float*)d_in[16];
    const float* mb2      = (const float*)d_in[17];
    const float* bn2g     = (const float*)d_in[18];
    const float* bn2b     = (const float*)d_in[19];
    const int*   ei       = (const int*)d_in[20];
    const int*   batch    = (const int*)d_in[21];
    float* out = (float*)d_out;

    float* xb = nullptr;
    cudaGetSymbolAddress((void**)&xb, g_xb);

    // launch #1: pe passthrough into second half of the output
    if (out_size >= (int)(2u * NN * 64)) {
        copy_pe_kernel<<<NN * 16 / 256, 256>>>(pe, out + (size_t)NN * 64);
    }
    // launch #2: layer-invariant complex edge features + edge graph ids
    z_kernel<<<EE / 8, 256>>>(pe, ei, batch);

    for (int l = 0; l < LL; l++) {
        const float* xcur = (l == 0) ? x : (const float*)xb;
        float* xout = (l == LL - 1) ? out : xb;
        // launch #3 (l=0): zero agg/stats + phi + fuse in ONE kernel
        prep_kernel<<<NN * 16 / 256, 256>>>(Lam, pw1, pb1, pw2, pb2,
                                            enc_w, enc_b, lin_w, lin_b, l);
        // launch #4 (l=0): edge kernel — lands in the ncu-profiled slot
        edge_kernel<<<EE / 256, 256>>>(edge_attr, xcur, ei);
        nodeA_kernel<<<NN / 32, 256>>>(xcur, mw1, mb1, l);
        nodeB_kernel<<<NN / 32, 256>>>(mw2, mb2, bn1g, bn1b, l);
        bn_apply_kernel<<<NN * 64 / 256, 256>>>(bn2g, bn2b, xout, l, (l != LL - 1) ? 1 : 0);
    }
}

// round 9
// speedup vs baseline: 1.6692x; 1.3395x over previous
#include <cuda_runtime.h>
#include <cuda_bf16.h>
#include <cstdint>

#define NN 100000
#define EE 800000
#define QMM 32
#define BB 100
#define LL 4
#define EPS_BN 1e-5f
#define SLOTMAX 812800          // EE + 128*BB
#define MAXT 6350               // SLOTMAX / 128

// dynamic-smem byte offsets; A/B rows padded to 144B (72 bf16) => conflict-free frags
#define OA1H 0
#define OA1L 18432
#define OA2H 36864
#define OA2L 55296
#define OB1H 73728
#define OB1L 82944
#define OB2H 92160
#define OB2L 101376
#define SMEM_EDGE 110592
#define OD 0                    // D overlay (128 x 272B = 34816B) over dead A1h/A1l

// ---------------- scratch (static __device__ — zero-initialized at load) ----------------
__device__ __nv_bfloat16 g_A1h[(size_t)SLOTMAX * 64];   // z hi   (slot-major)
__device__ __nv_bfloat16 g_A1l[(size_t)SLOTMAX * 64];   // z lo
__device__ __nv_bfloat16 g_A2h[(size_t)SLOTMAX * 64];   // edge_attr hi
__device__ __nv_bfloat16 g_A2l[(size_t)SLOTMAX * 64];   // edge_attr lo
__device__ __nv_bfloat16 g_B1h[(size_t)BB * 4096];      // per-graph W1b hi [b][c][k]
__device__ __nv_bfloat16 g_B1l[(size_t)BB * 4096];
__device__ __nv_bfloat16 g_B2h[4096];                   // shared W2 [c][k]
__device__ __nv_bfloat16 g_B2l[4096];
__device__ int   g_ssrc[SLOTMAX];     // src node per slot (-1 = pad)
__device__ int   g_sdst[SLOTMAX];
__device__ int   g_slot[EE];
__device__ int   g_gcnt[128], g_gcur[128];
__device__ int   g_tile_g[MAXT];      // graph id per tile (-1 = empty)
__device__ float g_agg[(size_t)NN * 64];
__device__ float g_y1[(size_t)NN * 64];
__device__ float g_y2[(size_t)NN * 64];
__device__ float g_xb[(size_t)NN * 64];
__device__ float g_wtab[BB * QMM];
__device__ float g_Wc[128 * 64];
__device__ float g_bc[64];
__device__ float g_stats[256];

// ---------------- helpers ----------------
__device__ __forceinline__ unsigned long long pack2(float a, float b) {
    unsigned long long r;
    asm("mov.b64 %0, {%1, %2};" : "=l"(r) : "f"(a), "f"(b));
    return r;
}
__device__ __forceinline__ void ffma2(unsigned long long& d, unsigned long long a, unsigned long long b) {
    asm("fma.rn.f32x2 %0, %1, %2, %0;" : "+l"(d) : "l"(a), "l"(b));
}
__device__ __forceinline__ float2 unpack2(unsigned long long v) {
    float2 r;
    asm("mov.b64 {%0, %1}, %2;" : "=f"(r.x), "=f"(r.y) : "l"(v));
    return r;
}
__device__ __forceinline__ void red_add_v4(float* p, float a, float b, float c, float d) {
    asm volatile("red.global.add.v4.f32 [%0], {%1, %2, %3, %4};"
                 :: "l"(p), "f"(a), "f"(b), "f"(c), "f"(d) : "memory");
}
__device__ __forceinline__ void mma16816(float* c, const uint32_t* a, const uint32_t* b) {
    asm volatile(
        "mma.sync.aligned.m16n8k16.row.col.f32.bf16.bf16.f32 "
        "{%0,%1,%2,%3}, {%4,%5,%6,%7}, {%8,%9}, {%0,%1,%2,%3};"
        : "+f"(c[0]), "+f"(c[1]), "+f"(c[2]), "+f"(c[3])
        : "r"(a[0]), "r"(a[1]), "r"(a[2]), "r"(a[3]), "r"(b[0]), "r"(b[1]));
}

// ---------------- one-time kernels ----------------
__global__ void copy_pe_kernel(const float* __restrict__ pe, float* __restrict__ out) {
    size_t i = (size_t)blockIdx.x * 256 + threadIdx.x;
    ((float4*)out)[i] = ((const float4*)pe)[i];
}
__global__ void setup_kernel() {
    int i = blockIdx.x * 256 + threadIdx.x;
    if (i < SLOTMAX) g_ssrc[i] = -1;
    if (blockIdx.x == 0 && threadIdx.x < 128) g_gcnt[threadIdx.x] = 0;
}
__global__ void count_kernel(const int* __restrict__ ei, const int* __restrict__ batch) {
    int e = blockIdx.x * 256 + threadIdx.x;
    if (e < EE) atomicAdd(&g_gcnt[batch[ei[e]]], 1);
}
__global__ __launch_bounds__(128) void bucket_scan_kernel() {
    __shared__ int sNT[128];
    __shared__ int sTot;
    int t = threadIdx.x;
    int cnt = (t < BB) ? g_gcnt[t] : 0;
    int nt = (cnt + 127) >> 7;
    sNT[t] = nt;
    __syncthreads();
    for (int off = 1; off < 128; off <<= 1) {
        int v = (t >= off) ? sNT[t - off] : 0;
        __syncthreads();
        sNT[t] += v;
        __syncthreads();
    }
    int excl = sNT[t] - nt;
    if (t < BB) {
        g_gcur[t] = excl * 128;
        for (int j = 0; j < nt; j++) g_tile_g[excl + j] = t;
    }
    if (t == 127) sTot = sNT[127];
    __syncthreads();
    for (int i = sTot + t; i < MAXT; i += 128) g_tile_g[i] = -1;
}
__global__ void fill_kernel(const int* __restrict__ ei, const int* __restrict__ batch) {
    int e = blockIdx.x * 256 + threadIdx.x;
    if (e >= EE) return;
    int b = batch[ei[e]];
    g_slot[e] = atomicAdd(&g_gcur[b], 1);
}
// z = pe[src]*conj(pe[dst]); bf16 hi/lo of [z_re|z_im] and edge_attr, by slot
__global__ __launch_bounds__(256) void convert_kernel(const float* __restrict__ pe,
                                                      const float* __restrict__ edge_attr,
                                                      const int* __restrict__ ei) {
    int e = blockIdx.x * 8 + (threadIdx.x >> 5);
    int qm = threadIdx.x & 31;
    int src = ei[e];
    int dst = ei[EE + e];
    int slot = g_slot[e];
    const float2* pe2 = (const float2*)pe;
    float2 zs = pe2[(size_t)src * 32 + qm];
    float2 zd = pe2[(size_t)dst * 32 + qm];
    float zr = zs.x * zd.x + zs.y * zd.y;
    float zi = zs.y * zd.x - zs.x * zd.y;
    size_t base = (size_t)slot * 64;
    __nv_bfloat16 h;
    h = __float2bfloat16(zr); g_A1h[base + qm] = h;
    g_A1l[base + qm] = __float2bfloat16(zr - __bfloat162float(h));
    h = __float2bfloat16(zi); g_A1h[base + 32 + qm] = h;
    g_A1l[base + 32 + qm] = __float2bfloat16(zi - __bfloat162float(h));
    float a0 = edge_attr[(size_t)e * 64 + qm];
    float a1 = edge_attr[(size_t)e * 64 + 32 + qm];
    h = __float2bfloat16(a0); g_A2h[base + qm] = h;
    g_A2l[base + qm] = __float2bfloat16(a0 - __bfloat162float(h));
    h = __float2bfloat16(a1); g_A2h[base + 32 + qm] = h;
    g_A2l[base + 32 + qm] = __float2bfloat16(a1 - __bfloat162float(h));
    if (qm == 0) { g_ssrc[slot] = src; g_sdst[slot] = dst; }
}

// ---------------- per-layer prep ----------------
__global__ void prep_kernel(const float* __restrict__ Lam, const float* __restrict__ pw1,
                            const float* __restrict__ pb1, const float* __restrict__ pw2,
                            const float* __restrict__ pb2,
                            const float* __restrict__ enc_w, const float* __restrict__ enc_b,
                            const float* __restrict__ lin_w, const float* __restrict__ lin_b,
                            int l) {
    size_t i = (size_t)blockIdx.x * 256 + threadIdx.x;
    ((float4*)g_agg)[i] = make_float4(0.f, 0.f, 0.f, 0.f);
    int b = blockIdx.x, t = threadIdx.x;
    if (b == 0) g_stats[t] = 0.f;
    if (b < 64 && t < 64) {
        int k = b, hh = t;
        const float* ew = enc_w + (size_t)l * 64 * 64;
        const float* lw = lin_w + (size_t)l * 64 * 64;
        float s = 0.f;
        for (int j = 0; j < 64; j++) s += ew[k * 64 + j] * lw[j * 64 + hh];
        g_Wc[k * 64 + hh] = s;
        g_Wc[(64 + k) * 64 + hh] = lw[k * 64 + hh];
        if (k == 0) {
            float bias = lin_b[l * 64 + hh];
            for (int j = 0; j < 64; j++) bias += enc_b[l * 64 + j] * lw[j * 64 + hh];
            g_bc[hh] = bias;
        }
    } else if (b >= 64 && b < 77) {
        int idx = (b - 64) * 256 + t;
        if (idx < BB * QMM) {
            float lam = Lam[idx];
            float s = pb2[l];
#pragma unroll
            for (int j = 0; j < 16; j++) {
                float h = fmaxf(lam * pw1[l * 16 + j] + pb1[l * 16 + j], 0.f);
                s += h * pw2[l * 16 + j];
            }
            g_wtab[idx] = s;
        }
    }
}

// per-graph bf16 weights: B1[b][c][k] = we_b[k&31]*Wc[k][c] hi/lo; B2[c][k] = Wc[64+k][c]
__global__ void wprep_kernel(int l) {
    int b = blockIdx.x, t = threadIdx.x;
    if (b < BB) {
#pragma unroll 4
        for (int i = 0; i < 16; i++) {
            int idx = i * 256 + t;
            int c = idx >> 6, k = idx & 63;
            float w = g_wtab[b * 32 + (k & 31)] * g_Wc[k * 64 + c];
            __nv_bfloat16 h = __float2bfloat16(w);
            g_B1h[(size_t)b * 4096 + idx] = h;
            g_B1l[(size_t)b * 4096 + idx] = __float2bfloat16(w - __bfloat162float(h));
        }
    } else {
#pragma unroll 4
        for (int i = 0; i < 16; i++) {
            int idx = i * 256 + t;
            int c = idx >> 6, k = idx & 63;
            float w = g_Wc[(64 + k) * 64 + c];
            __nv_bfloat16 h = __float2bfloat16(w);
            g_B2h[idx] = h;
            g_B2l[idx] = __float2bfloat16(w - __bfloat162float(h));
        }
    }
}

// ---------------- edge kernel: HMMA bf16-split per 128-edge tile ----------------
__global__ __launch_bounds__(256) void edge_mma_kernel(const float* __restrict__ xcur) {
    extern __shared__ char sm[];
    int t = threadIdx.x;
    int lane = t & 31, w = t >> 5;
    int tile = blockIdx.x;
    int b = g_tile_g[tile];
    if (b < 0) b = 0;

    // ---- stage A (4 x 128x64 bf16) and B (4 x 64x64 bf16), rows padded to 144B ----
    {
        const __nv_bfloat16* gA[4] = {g_A1h, g_A1l, g_A2h, g_A2l};
        const int offA[4] = {OA1H, OA1L, OA2H, OA2L};
#pragma unroll
        for (int m = 0; m < 4; m++) {
            const uint4* gp = (const uint4*)(gA[m] + (size_t)tile * 8192);
#pragma unroll
            for (int i = 0; i < 4; i++) {
                int lin = i * 256 + t;   // 1024 chunks of 16B; row=lin>>3, col-chunk=lin&7
                uint4 v = gp[lin];
                *(uint4*)(sm + offA[m] + (lin >> 3) * 144 + (lin & 7) * 16) = v;
            }
        }
        const __nv_bfloat16* gB[4] = {g_B1h + (size_t)b * 4096, g_B1l + (size_t)b * 4096,
                                      g_B2h, g_B2l};
        const int offB[4] = {OB1H, OB1L, OB2H, OB2L};
#pragma unroll
        for (int m = 0; m < 4; m++) {
            const uint4* gp = (const uint4*)gB[m];
#pragma unroll
            for (int i = 0; i < 2; i++) {
                int lin = i * 256 + t;   // 512 chunks
                uint4 v = gp[lin];
                *(uint4*)(sm + offB[m] + (lin >> 3) * 144 + (lin & 7) * 16) = v;
            }
        }
    }
    __syncthreads();

    int wm = w & 3, wn = w >> 2;        // warp tile: 32 edges x 32 ch
    int g = lane >> 2, tig = lane & 3;
    float acc[2][4][4];
#pragma unroll
    for (int mt = 0; mt < 2; mt++)
#pragma unroll
        for (int nt = 0; nt < 4; nt++)
#pragma unroll
            for (int j = 0; j < 4; j++) acc[mt][nt][j] = 0.f;

    const int aB[6] = {OA1H, OA1L, OA1H, OA2H, OA2L, OA2H};
    const int bB[6] = {OB1H, OB1H, OB1L, OB2H, OB2H, OB2L};
    uint32_t aRow = (uint32_t)(wm * 32 + g) * 144 + tig * 4;
    uint32_t bRow = (uint32_t)(wn * 32 + g) * 144 + tig * 4;

#pragma unroll
    for (int p = 0; p < 6; p++) {
        const char* pa = sm + aB[p];
        const char* pb = sm + bB[p];
#pragma unroll
        for (int kc = 0; kc < 4; kc++) {
            int ko = kc * 32;   // k0*2 bytes
            uint32_t a[2][4], bf[4][2];
#pragma unroll
            for (int mt = 0; mt < 2; mt++) {
                const char* base = pa + aRow + mt * (16 * 144) + ko;
                a[mt][0] = *(const uint32_t*)(base);
                a[mt][1] = *(const uint32_t*)(base + 8 * 144);
                a[mt][2] = *(const uint32_t*)(base + 16);
                a[mt][3] = *(const uint32_t*)(base + 8 * 144 + 16);
            }
#pragma unroll
            for (int nt = 0; nt < 4; nt++) {
                const char* base = pb + bRow + nt * (8 * 144) + ko;
                bf[nt][0] = *(const uint32_t*)(base);
                bf[nt][1] = *(const uint32_t*)(base + 16);
            }
#pragma unroll
            for (int mt = 0; mt < 2; mt++)
#pragma unroll
                for (int nt = 0; nt < 4; nt++)
                    mma16816(acc[mt][nt], a[mt], bf[nt]);
        }
    }
    __syncthreads();   // A region dead; safe to overlay D

    // ---- write D frags to smem (row stride 272B) ----
#pragma unroll
    for (int mt = 0; mt < 2; mt++) {
        int r0 = wm * 32 + mt * 16 + g;
#pragma unroll
        for (int nt = 0; nt < 4; nt++) {
            int c = wn * 32 + nt * 8 + tig * 2;
            *(float2*)(sm + OD + r0 * 272 + c * 4) = make_float2(acc[mt][nt][0], acc[mt][nt][1]);
            *(float2*)(sm + OD + (r0 + 8) * 272 + c * 4) = make_float2(acc[mt][nt][2], acc[mt][nt][3]);
        }
    }
    __syncthreads();

    // ---- epilogue: 2 threads per edge, +bias+x[src], relu, vector-atomic scatter ----
    int edge = t >> 1, half = t & 1;
    int slot = tile * 128 + edge;
    int srcn = g_ssrc[slot];
    if (srcn >= 0) {
        int dstn = g_sdst[slot];
        const float* Dr = (const float*)(sm + OD + edge * 272 + half * 128);
        const float* xr = xcur + (size_t)srcn * 64 + half * 32;
        const float* br = g_bc + half * 32;
        float* dp = g_agg + (size_t)dstn * 64 + half * 32;
#pragma unroll
        for (int q = 0; q < 8; q++) {
            float4 dv = *(const float4*)(Dr + q * 4);
            float4 xv = *(const float4*)(xr + q * 4);
            float4 bc = *(const float4*)(br + q * 4);
            red_add_v4(dp + q * 4,
                       fmaxf(dv.x + bc.x + xv.x, 0.f), fmaxf(dv.y + bc.y + xv.y, 0.f),
                       fmaxf(dv.z + bc.z + xv.z, 0.f), fmaxf(dv.w + bc.w + xv.w, 0.f));
        }
    }
}

// ---------------- node kernels (unchanged from R7) ----------------
__global__ __launch_bounds__(256) void nodeA_kernel(const float* __restrict__ xcur,
                                                    const float* __restrict__ W,
                                                    const float* __restrict__ bias, int l) {
    __shared__ float sW[64 * 64];
    __shared__ float sA[64 * 32];
    __shared__ float sRs[256], sRq[256];
    int t = threadIdx.x;
    int n0 = blockIdx.x * 32;
    {
        const float4* Wv = (const float4*)(W + (size_t)l * 4096);
        float4* sWv = (float4*)sW;
#pragma unroll
        for (int i = 0; i < 4; i++) sWv[t + 256 * i] = Wv[t + 256 * i];
    }
    int n_loc = t & 31, part = t >> 5;
    int k0 = part * 8;
    {
        size_t base = (size_t)(n0 + n_loc) * 64 + k0;
        float4 x0 = *(const float4*)(xcur + base);
        float4 x1 = *(const float4*)(xcur + base + 4);
        float4 a0 = *(const float4*)(g_agg + base);
        float4 a1 = *(const float4*)(g_agg + base + 4);
        sA[(k0 + 0) * 32 + n_loc] = x0.x + a0.x;
        sA[(k0 + 1) * 32 + n_loc] = x0.y + a0.y;
        sA[(k0 + 2) * 32 + n_loc] = x0.z + a0.z;
        sA[(k0 + 3) * 32 + n_loc] = x0.w + a0.w;
        sA[(k0 + 4) * 32 + n_loc] = x1.x + a1.x;
        sA[(k0 + 5) * 32 + n_loc] = x1.y + a1.y;
        sA[(k0 + 6) * 32 + n_loc] = x1.z + a1.z;
        sA[(k0 + 7) * 32 + n_loc] = x1.w + a1.w;
    }
    __syncthreads();

    int tx = t & 63, ty = t >> 6;
    unsigned long long acc[4] = {0ull, 0ull, 0ull, 0ull};
#pragma unroll 8
    for (int k = 0; k < 64; k++) {
        float w = sW[k * 64 + tx];
        unsigned long long w2 = pack2(w, w);
        const ulonglong2* ap = (const ulonglong2*)(sA + k * 32 + ty * 8);
        ulonglong2 a01 = ap[0];
        ulonglong2 a23 = ap[1];
        ffma2(acc[0], a01.x, w2);
        ffma2(acc[1], a01.y, w2);
        ffma2(acc[2], a23.x, w2);
        ffma2(acc[3], a23.y, w2);
    }
    float bb = bias[l * 64 + tx];
    float s = 0.f, q = 0.f;
#pragma unroll
    for (int p = 0; p < 4; p++) {
        float2 v = unpack2(acc[p]);
        int na = ty * 8 + p * 2;
        float yA = v.x + bb, yB = v.y + bb;
        g_y1[(size_t)(n0 + na) * 64 + tx] = yA;
        g_y1[(size_t)(n0 + na + 1) * 64 + tx] = yB;
        s += yA + yB;
        q += yA * yA + yB * yB;
    }
    sRs[t] = s;
    sRq[t] = q;
    __syncthreads();
    if (t < 64) {
        s = sRs[t] + sRs[64 + t] + sRs[128 + t] + sRs[192 + t];
        q = sRq[t] + sRq[64 + t] + sRq[128 + t] + sRq[192 + t];
        atomicAdd(&g_stats[t], s);
        atomicAdd(&g_stats[64 + t], q);
    }
}

__global__ __launch_bounds__(256) void nodeB_kernel(const float* __restrict__ W,
                                                    const float* __restrict__ bias,
                                                    const float* __restrict__ bg,
                                                    const float* __restrict__ bnb, int l) {
    __shared__ float sW[64 * 64];
    __shared__ float sA[64 * 32];
    __shared__ float sSc[64], sSh[64];
    __shared__ float sRs[256], sRq[256];
    int t = threadIdx.x;
    int n0 = blockIdx.x * 32;
    {
        const float4* Wv = (const float4*)(W + (size_t)l * 4096);
        float4* sWv = (float4*)sW;
#pragma unroll
        for (int i = 0; i < 4; i++) sWv[t + 256 * i] = Wv[t + 256 * i];
    }
    if (t < 64) {
        float mu = g_stats[t] * (1.0f / NN);
        float var = g_stats[64 + t] * (1.0f / NN) - mu * mu;
        float rs = rsqrtf(var + EPS_BN);
        float sc = rs * bg[l * 64 + t];
        sSc[t] = sc;
        sSh[t] = bnb[l * 64 + t] - mu * sc;
    }
    __syncthreads();
    int n_loc = t & 31, part = t >> 5;
    int k0 = part * 8;
    {
        size_t base = (size_t)(n0 + n_loc) * 64 + k0;
        float4 y0 = *(const float4*)(g_y1 + base);
        float4 y1v = *(const float4*)(g_y1 + base + 4);
        sA[(k0 + 0) * 32 + n_loc] = fmaxf(y0.x * sSc[k0 + 0] + sSh[k0 + 0], 0.f);
        sA[(k0 + 1) * 32 + n_loc] = fmaxf(y0.y * sSc[k0 + 1] + sSh[k0 + 1], 0.f);
        sA[(k0 + 2) * 32 + n_loc] = fmaxf(y0.z * sSc[k0 + 2] + sSh[k0 + 2], 0.f);
        sA[(k0 + 3) * 32 + n_loc] = fmaxf(y0.w * sSc[k0 + 3] + sSh[k0 + 3], 0.f);
        sA[(k0 + 4) * 32 + n_loc] = fmaxf(y1v.x * sSc[k0 + 4] + sSh[k0 + 4], 0.f);
        sA[(k0 + 5) * 32 + n_loc] = fmaxf(y1v.y * sSc[k0 + 5] + sSh[k0 + 5], 0.f);
        sA[(k0 + 6) * 32 + n_loc] = fmaxf(y1v.z * sSc[k0 + 6] + sSh[k0 + 6], 0.f);
        sA[(k0 + 7) * 32 + n_loc] = fmaxf(y1v.w * sSc[k0 + 7] + sSh[k0 + 7], 0.f);
    }
    __syncthreads();

    int tx = t & 63, ty = t >> 6;
    unsigned long long acc[4] = {0ull, 0ull, 0ull, 0ull};
#pragma unroll 8
    for (int k = 0; k < 64; k++) {
        float w = sW[k * 64 + tx];
        unsigned long long w2 = pack2(w, w);
        const ulonglong2* ap = (const ulonglong2*)(sA + k * 32 + ty * 8);
        ulonglong2 a01 = ap[0];
        ulonglong2 a23 = ap[1];
        ffma2(acc[0], a01.x, w2);
        ffma2(acc[1], a01.y, w2);
        ffma2(acc[2], a23.x, w2);
        ffma2(acc[3], a23.y, w2);
    }
    float bb = bias[l * 64 + tx];
    float s = 0.f, q = 0.f;
#pragma unroll
    for (int p = 0; p < 4; p++) {
        float2 v = unpack2(acc[p]);
        int na = ty * 8 + p * 2;
        float yA = v.x + bb, yB = v.y + bb;
        g_y2[(size_t)(n0 + na) * 64 + tx] = yA;
        g_y2[(size_t)(n0 + na + 1) * 64 + tx] = yB;
        s += yA + yB;
        q += yA * yA + yB * yB;
    }
    sRs[t] = s;
    sRq[t] = q;
    __syncthreads();
    if (t < 64) {
        s = sRs[t] + sRs[64 + t] + sRs[128 + t] + sRs[192 + t];
        q = sRq[t] + sRq[64 + t] + sRq[128 + t] + sRq[192 + t];
        atomicAdd(&g_stats[128 + t], s);
        atomicAdd(&g_stats[192 + t], q);
    }
}

__global__ void bn_apply_kernel(const float* __restrict__ bg, const float* __restrict__ bnb,
                                float* __restrict__ xout, int l, int do_relu) {
    int i = blockIdx.x * 256 + threadIdx.x;
    int h = i & 63;
    float mu = g_stats[128 + h] * (1.0f / NN);
    float var = g_stats[192 + h] * (1.0f / NN) - mu * mu;
    float rs = rsqrtf(var + EPS_BN);
    float sc = rs * bg[l * 64 + h];
    float sh = bnb[l * 64 + h] - mu * sc;
    float v = g_y2[i] * sc + sh;
    if (do_relu) v = fmaxf(v, 0.f);
    xout[i] = v;
}

// ---------------- launcher ----------------
extern "C" void kernel_launch(void* const* d_in, const int* in_sizes, int n_in,
                              void* d_out, int out_size) {
    const float* x        = (const float*)d_in[0];
    const float* pe       = (const float*)d_in[1];
    const float* Lam      = (const float*)d_in[2];
    const float* edge_attr= (const float*)d_in[3];
    const float* pw1      = (const float*)d_in[4];
    const float* pb1      = (const float*)d_in[5];
    const float* pw2      = (const float*)d_in[6];
    const float* pb2      = (const float*)d_in[7];
    const float* enc_w    = (const float*)d_in[8];
    const float* enc_b    = (const float*)d_in[9];
    const float* lin_w    = (const float*)d_in[10];
    const float* lin_b    = (const float*)d_in[11];
    const float* mw1      = (const float*)d_in[12];
    const float* mb1      = (const float*)d_in[13];
    const float* bn1g     = (const float*)d_in[14];
    const float* bn1b     = (const float*)d_in[15];
    const float* mw2      = (const float*)d_in[16];
    const float* mb2      = (const float*)d_in[17];
    const float* bn2g     = (const float*)d_in[18];
    const float* bn2b     = (const float*)d_in[19];
    const int*   ei       = (const int*)d_in[20];
    const int*   batch    = (const int*)d_in[21];
    float* out = (float*)d_out;

    float* xb = nullptr;
    cudaGetSymbolAddress((void**)&xb, g_xb);
    cudaFuncSetAttribute(edge_mma_kernel, cudaFuncAttributeMaxDynamicSharedMemorySize, SMEM_EDGE);

    if (out_size >= (int)(2u * NN * 64)) {
        copy_pe_kernel<<<NN * 16 / 256, 256>>>(pe, out + (size_t)NN * 64);
    }
    // one-time: bucket edges by graph, slot map, bf16 conversion
    setup_kernel<<<(SLOTMAX + 255) / 256, 256>>>();
    count_kernel<<<EE / 256, 256>>>(ei, batch);
    bucket_scan_kernel<<<1, 128>>>();
    fill_kernel<<<EE / 256, 256>>>(ei, batch);
    convert_kernel<<<EE / 8, 256>>>(pe, edge_attr, ei);

    for (int l = 0; l < LL; l++) {
        const float* xcur = (l == 0) ? x : (const float*)xb;
        float* xout = (l == LL - 1) ? out : xb;
        prep_kernel<<<NN * 16 / 256, 256>>>(Lam, pw1, pb1, pw2, pb2,
                                            enc_w, enc_b, lin_w, lin_b, l);
        wprep_kernel<<<BB + 1, 256>>>(l);
        edge_mma_kernel<<<MAXT, 256, SMEM_EDGE>>>(xcur);
        nodeA_kernel<<<NN / 32, 256>>>(xcur, mw1, mb1, l);
        nodeB_kernel<<<NN / 32, 256>>>(mw2, mb2, bn1g, bn1b, l);
        bn_apply_kernel<<<NN * 64 / 256, 256>>>(bn2g, bn2b, xout, l, (l != LL - 1) ? 1 : 0);
    }
}